// round 17
// baseline (speedup 1.0000x reference)
#include <cuda_runtime.h>
#include <cuda_bf16.h>
#include <math.h>

#define FNUM  32
#define BATCH 2048
#define KD    64
#define HD    64
#define WROW  72     // Wt row stride (bf16)
#define NA    20     // same-field chunks (both halves share fs)
#define NB    12     // mixed chunks (each half same-fs, fs differs; pads here)

__device__ __forceinline__ unsigned cvt_bf16x2(float hi, float lo) {
    unsigned r;
    asm("cvt.rn.bf16x2.f32 %0, %1, %2;" : "=r"(r) : "f"(hi), "f"(lo));
    return r;
}

__device__ __forceinline__ unsigned hmul2u(unsigned a, unsigned b) {
    unsigned r;
    asm("mul.rn.bf16x2 %0, %1, %2;" : "=r"(r) : "r"(a), "r"(b));
    return r;
}

__device__ __forceinline__ void mma16816(float* c, const unsigned* a, unsigned b0, unsigned b1) {
    asm volatile("mma.sync.aligned.m16n8k16.row.col.f32.bf16.bf16.f32 "
                 "{%0,%1,%2,%3}, {%4,%5,%6,%7}, {%8,%9}, {%0,%1,%2,%3};"
                 : "+f"(c[0]), "+f"(c[1]), "+f"(c[2]), "+f"(c[3])
                 : "r"(a[0]), "r"(a[1]), "r"(a[2]), "r"(a[3]), "r"(b0), "r"(b1));
}

// ---- compile-time schedule: 32 chunks of 16 rows; every 8-row half shares one field ----
struct Sched {
    unsigned char fsA[NA];        // shared field for both halves of chunk
    unsigned char fpA[NA][16];    // partner field; rows 0-7 half0 (quad), 8-15 half1
    unsigned char fsB[NB][2];     // per-half shared fields
    unsigned char fpB[NB][16];    // 255 = pad row
};
static constexpr Sched make_sched() {
    Sched s{};
    unsigned char hfs[64] = {};
    unsigned char hfp[64][8] = {};
    bool isp[64] = {};
    int nh = 0;
    int li[128] = {}; int lj[128] = {}; int nl = 0;
    for (int i = 0; i < 32; i++) {                 // full same-i halves, leftovers pooled
        int c = 31 - i;
        int full = c / 8;
        for (int g = 0; g < full; g++) {
            hfs[nh] = (unsigned char)i;
            for (int r = 0; r < 8; r++) hfp[nh][r] = (unsigned char)(i + 1 + g * 8 + r);
            nh++;
        }
        for (int j = i + 1 + full * 8; j <= 31; j++) { li[nl] = i; lj[nl] = j; nl++; }
    }
    for (int j = 31; j >= 0; j--) {                // same-j halves from leftovers
        int buf[32] = {}; int n = 0;
        for (int t = 0; t < nl; t++) if (lj[t] == j) buf[n++] = li[t];
        int g = 0;
        for (; g + 8 <= n; g += 8) {
            hfs[nh] = (unsigned char)j;
            for (int r = 0; r < 8; r++) hfp[nh][r] = (unsigned char)buf[g + r];
            nh++;
        }
        if (g < n) {                               // partial half (pads)
            hfs[nh] = (unsigned char)j;
            for (int r = 0; r < 8; r++) hfp[nh][r] = (unsigned char)((g + r < n) ? buf[g + r] : 255);
            isp[nh] = true;
            nh++;
        }
    }
    bool used[64] = {};
    int na = 0;
    for (int a = 0; a < 64 && na < NA; a++) {      // pair equal-fs full halves -> type A
        if (used[a] || isp[a]) continue;
        for (int b = a + 1; b < 64; b++) {
            if (used[b] || isp[b] || hfs[b] != hfs[a]) continue;
            s.fsA[na] = hfs[a];
            for (int r = 0; r < 8; r++) { s.fpA[na][r] = hfp[a][r]; s.fpA[na][8 + r] = hfp[b][r]; }
            used[a] = true; used[b] = true; na++;
            break;
        }
    }
    int rem[64] = {}; int nr = 0;
    for (int a = 0; a < 64; a++) if (!used[a]) rem[nr++] = a;
    for (int t2 = 0; t2 + 1 < nr; t2 += 2) {       // remaining halves -> type B
        int a = rem[t2], b = rem[t2 + 1];
        int nb = t2 / 2;
        s.fsB[nb][0] = hfs[a]; s.fsB[nb][1] = hfs[b];
        for (int r = 0; r < 8; r++) { s.fpB[nb][r] = hfp[a][r]; s.fpB[nb][8 + r] = hfp[b][r]; }
    }
    return s;
}
__constant__ Sched dsched = make_sched();

// physical placement of logical bf16x2-pair m (=k/2): thread q owns 16B segs 2q, 2q+1.
// 16B segments XOR-swizzled by (field & 7).
__device__ __forceinline__ int vperm_idx(int m, int f) {
    int kc = m >> 3, r = m & 7, q = r & 3, hi = r >> 2;
    int pu = q * 8 + kc * 2 + hi;
    return ((((pu >> 2) ^ (f & 7)) << 2)) | (pu & 3);
}

// one 16-row chunk: build A frags, g-MMA, hid-GEMM, fused epilogue.
// returns q==0-lane contribution slo*g0 + shi*g1 (masked).
template<bool SAME, bool MASK>
__device__ __forceinline__ float do_chunk(
    const unsigned (*__restrict__ Vbb)[32],
    int fs0, int fs1, int fp0, int fp1, float m0, float m1, int q,
    const unsigned (&Bf)[8][8], const unsigned (&pc0)[4], const unsigned (&pc1)[4],
    const float2 (&bh0)[8], const float2 (&bh1)[8])
{
    int s0 = 2 * q, s1 = s0 + 1;
    const uint4* Rs0 = reinterpret_cast<const uint4*>(Vbb[fs0]);
    uint4 i0a = Rs0[s0 ^ (fs0 & 7)], i0b = Rs0[s1 ^ (fs0 & 7)];
    uint4 i1a, i1b;
    if (SAME) { i1a = i0a; i1b = i0b; }
    else {
        const uint4* Rs1 = reinterpret_cast<const uint4*>(Vbb[fs1]);
        i1a = Rs1[s0 ^ (fs1 & 7)]; i1b = Rs1[s1 ^ (fs1 & 7)];
    }
    const uint4* Rp0 = reinterpret_cast<const uint4*>(Vbb[fp0]);
    const uint4* Rp1 = reinterpret_cast<const uint4*>(Vbb[fp1]);
    uint4 j0a = Rp0[s0 ^ (fp0 & 7)], j0b = Rp0[s1 ^ (fp0 & 7)];
    uint4 j1a = Rp1[s0 ^ (fp1 & 7)], j1b = Rp1[s1 ^ (fp1 & 7)];

    unsigned A[4][4];
    A[0][0] = hmul2u(i0a.x, j0a.x);  A[0][2] = hmul2u(i0a.y, j0a.y);
    A[1][0] = hmul2u(i0a.z, j0a.z);  A[1][2] = hmul2u(i0a.w, j0a.w);
    A[2][0] = hmul2u(i0b.x, j0b.x);  A[2][2] = hmul2u(i0b.y, j0b.y);
    A[3][0] = hmul2u(i0b.z, j0b.z);  A[3][2] = hmul2u(i0b.w, j0b.w);
    A[0][1] = hmul2u(i1a.x, j1a.x);  A[0][3] = hmul2u(i1a.y, j1a.y);
    A[1][1] = hmul2u(i1a.z, j1a.z);  A[1][3] = hmul2u(i1a.w, j1a.w);
    A[2][1] = hmul2u(i1b.x, j1b.x);  A[2][3] = hmul2u(i1b.y, j1b.y);
    A[3][1] = hmul2u(i1b.z, j1b.z);  A[3][3] = hmul2u(i1b.w, j1b.w);

    float accg[4] = {0.f, 0.f, 0.f, 0.f};
    mma16816(accg, A[0], pc0[0], pc1[0]);
    mma16816(accg, A[1], pc0[1], pc1[1]);
    mma16816(accg, A[2], pc0[2], pc1[2]);
    mma16816(accg, A[3], pc0[3], pc1[3]);

    float slo = 0.0f, shi = 0.0f;
    #pragma unroll
    for (int nt = 0; nt < 8; nt += 2) {
        float acc0[4] = {0.f, 0.f, 0.f, 0.f};
        float acc1[4] = {0.f, 0.f, 0.f, 0.f};
        mma16816(acc0, A[0], Bf[nt][0], Bf[nt][1]);
        mma16816(acc0, A[1], Bf[nt][2], Bf[nt][3]);
        mma16816(acc0, A[2], Bf[nt][4], Bf[nt][5]);
        mma16816(acc0, A[3], Bf[nt][6], Bf[nt][7]);
        mma16816(acc1, A[0], Bf[nt + 1][0], Bf[nt + 1][1]);
        mma16816(acc1, A[1], Bf[nt + 1][2], Bf[nt + 1][3]);
        mma16816(acc1, A[2], Bf[nt + 1][4], Bf[nt + 1][5]);
        mma16816(acc1, A[3], Bf[nt + 1][6], Bf[nt + 1][7]);
        slo += fmaxf(acc0[0] + bh0[nt].x,     0.0f) * bh0[nt].y
             + fmaxf(acc0[1] + bh1[nt].x,     0.0f) * bh1[nt].y
             + fmaxf(acc1[0] + bh0[nt + 1].x, 0.0f) * bh0[nt + 1].y
             + fmaxf(acc1[1] + bh1[nt + 1].x, 0.0f) * bh1[nt + 1].y;
        shi += fmaxf(acc0[2] + bh0[nt].x,     0.0f) * bh0[nt].y
             + fmaxf(acc0[3] + bh1[nt].x,     0.0f) * bh1[nt].y
             + fmaxf(acc1[2] + bh0[nt + 1].x, 0.0f) * bh0[nt + 1].y
             + fmaxf(acc1[3] + bh1[nt + 1].x, 0.0f) * bh1[nt + 1].y;
    }

    slo += __shfl_xor_sync(0xffffffffu, slo, 1);
    slo += __shfl_xor_sync(0xffffffffu, slo, 2);
    shi += __shfl_xor_sync(0xffffffffu, shi, 1);
    shi += __shfl_xor_sync(0xffffffffu, shi, 2);
    float g0 = MASK ? accg[0] * m0 : accg[0];
    float g1 = MASK ? accg[2] * m1 : accg[2];
    return slo * g0 + shi * g1;
}

__global__ void __launch_bounds__(128, 3)
afm_kernel(const int* __restrict__ x, const float* __restrict__ emb,
           const float* __restrict__ at_w, const float* __restrict__ at_b,
           const float* __restrict__ at_h, const float* __restrict__ pvec,
           const float* __restrict__ w0, const float* __restrict__ w1,
           float* __restrict__ out)
{
    __shared__ __align__(16) unsigned       Vb[2][FNUM][32];   // bf16x2, permuted+swizzled
    __shared__ __align__(16) __nv_bfloat16  Wt[HD][WROW];      // Wt[n][k] = at_w[k][n]
    __shared__ __align__(8)  Sched          ssch;
    __shared__ float2          bhsh[HD];     // {at_b[h], at_h[h]}
    __shared__ float           psh[KD];
    __shared__ float           warpsum[2][4];
    __shared__ float           fm1sh[2];
    __shared__ int             xsh[2][FNUM];

    const int tid = threadIdx.x;
    const int b0  = blockIdx.x * 2;

    // --- fm1 + stage x indices, 2 batches ---
    if (tid < 64) {
        int bb = tid >> 5, f = tid & 31;
        int xv = x[f * BATCH + b0 + bb];
        xsh[bb][f] = xv;
        float v = w1[xv];
        #pragma unroll
        for (int o = 16; o; o >>= 1) v += __shfl_xor_sync(0xffffffffu, v, o);
        if (f == 0) fm1sh[bb] = v;
    }
    if (tid < HD) {
        bhsh[tid] = make_float2(at_b[tid], at_h[tid]);
        psh[tid]  = pvec[tid];
    }
    for (int t = tid; t < (int)sizeof(Sched); t += 128)
        ((char*)&ssch)[t] = ((const char*)&dsched)[t];
    __syncthreads();   // xsh visible

    // --- load V rows (fp32 gmem -> bf16x2 permuted smem), 64 rows, 2 threads/row ---
    {
        int row = tid >> 1, half = tid & 1;     // half: logical k 0..31 / 32..63
        int bb = row >> 5, f = row & 31;
        const float4* src = reinterpret_cast<const float4*>(emb + (size_t)xsh[bb][f] * KD) + half * 8;
        unsigned* dst = Vb[bb][f];
        #pragma unroll
        for (int u = 0; u < 8; u++) {
            float4 v4 = src[u];
            int m = half * 16 + 2 * u;
            dst[vperm_idx(m, f)]     = cvt_bf16x2(v4.y, v4.x);
            dst[vperm_idx(m + 1, f)] = cvt_bf16x2(v4.w, v4.z);
        }
    }
    // --- load W^T ---
    for (int idx = tid; idx < HD * KD; idx += 128) {
        int n = idx >> 6, k = idx & 63;
        Wt[n][k] = __float2bfloat16(at_w[k * HD + n]);
    }
    __syncthreads();

    const int lane = tid & 31;
    const int warp = tid >> 5;
    const int quad = lane >> 2;          // fragment row group (0..7)
    const int q    = lane & 3;           // fragment k/n sub-lane

    // per-thread (bias, at_h) for owned C columns: n = nt*8 + 2q + {0,1}
    float2 bh0[8], bh1[8];
    #pragma unroll
    for (int nt = 0; nt < 8; nt++) {
        int cb = nt * 8 + q * 2;
        bh0[nt] = bhsh[cb];
        bh1[nt] = bhsh[cb + 1];
    }

    // --- build all B fragments once by plain loads (logical k-order) ---
    unsigned Bf[8][8];
    #pragma unroll
    for (int nt = 0; nt < 8; nt++) {
        const __nv_bfloat16* wr = Wt[nt * 8 + quad];
        #pragma unroll
        for (int kc = 0; kc < 4; kc++) {
            Bf[nt][2 * kc]     = *reinterpret_cast<const unsigned*>(wr + 16 * kc + 2 * q);
            Bf[nt][2 * kc + 1] = *reinterpret_cast<const unsigned*>(wr + 16 * kc + 2 * q + 8);
        }
    }
    // --- p-vector B fragment (column 0 only: quad 0 lanes carry p, rest zero) ---
    unsigned pc0[4], pc1[4];
    #pragma unroll
    for (int kc = 0; kc < 4; kc++) {
        if (quad == 0) {
            pc0[kc] = cvt_bf16x2(psh[16 * kc + 2 * q + 1], psh[16 * kc + 2 * q]);
            pc1[kc] = cvt_bf16x2(psh[16 * kc + 2 * q + 9], psh[16 * kc + 2 * q + 8]);
        } else { pc0[kc] = 0u; pc1[kc] = 0u; }
    }

    for (int bb = 0; bb < 2; bb++) {
        float att = 0.0f;

        #pragma unroll
        for (int t = 0; t < 5; t++) {                     // type A: both halves same fs
            int ca = warp * 5 + t;
            int fs  = ssch.fsA[ca];
            int fp0 = ssch.fpA[ca][quad];
            int fp1 = ssch.fpA[ca][8 + quad];
            float ctr = do_chunk<true, false>(Vb[bb], fs, fs, fp0, fp1, 1.f, 1.f, q,
                                              Bf, pc0, pc1, bh0, bh1);
            if (q == 0) att += ctr;
        }
        #pragma unroll
        for (int t = 0; t < 3; t++) {                     // type B: per-half fs, pads masked
            int cb2 = warp * 3 + t;
            int fs0 = ssch.fsB[cb2][0], fs1 = ssch.fsB[cb2][1];
            int fp0 = ssch.fpB[cb2][quad];
            int fp1 = ssch.fpB[cb2][8 + quad];
            float m0 = 1.f, m1 = 1.f;
            if (fp0 == 255) { fp0 = fs0; m0 = 0.f; }
            if (fp1 == 255) { fp1 = fs1; m1 = 0.f; }
            float ctr = do_chunk<false, true>(Vb[bb], fs0, fs1, fp0, fp1, m0, m1, q,
                                              Bf, pc0, pc1, bh0, bh1);
            if (q == 0) att += ctr;
        }

        #pragma unroll
        for (int o = 16; o; o >>= 1) att += __shfl_xor_sync(0xffffffffu, att, o);
        if (lane == 0) warpsum[bb][warp] = att;
    }

    __syncthreads();
    if (tid < 2) {
        float logit = warpsum[tid][0] + warpsum[tid][1] + warpsum[tid][2] + warpsum[tid][3]
                    + fm1sh[tid] + w0[0];
        out[b0 + tid] = 1.0f / (1.0f + expf(-logit));
    }
}

extern "C" void kernel_launch(void* const* d_in, const int* in_sizes, int n_in,
                              void* d_out, int out_size) {
    const int*   x    = (const int*)d_in[0];
    const float* emb  = (const float*)d_in[1];
    const float* at_w = (const float*)d_in[2];
    const float* at_b = (const float*)d_in[3];
    const float* at_h = (const float*)d_in[4];
    const float* pvec = (const float*)d_in[5];
    const float* w0   = (const float*)d_in[6];
    const float* w1   = (const float*)d_in[7];
    float* out = (float*)d_out;
    afm_kernel<<<BATCH / 2, 128>>>(x, emb, at_w, at_b, at_h, pvec, w0, w1, out);
}